// round 2
// baseline (speedup 1.0000x reference)
#include <cuda_runtime.h>

#define NH   16
#define DH   64
#define HID  1024
#define NB   4
#define SL   2048
#define MROWS (NB*SL)   // 8192

// Scratch (device globals: allocation-free)
__device__ float g_Q[(size_t)NB*NH*SL*DH];   // [B,H,S,D]
__device__ float g_K[(size_t)NB*NH*SL*DH];
__device__ float g_V[(size_t)NB*NH*SL*DH];
__device__ float g_A[(size_t)NB*SL*HID];     // [B,S,HID] attention output

// ---------------------------------------------------------------------------
// 128x128x16 NT SGEMM body: Y[m][n] = sum_k A[m][k]*W[n][k] + bias[n]
// MODE 0: write to [B,H,S,D] (split heads). MODE 1: write [M][N] flat.
// ---------------------------------------------------------------------------
template<int MODE>
__device__ __forceinline__ void gemm128(const float* __restrict__ A,
                                        const float* __restrict__ W,
                                        const float* __restrict__ bias,
                                        float* __restrict__ out)
{
    __shared__ float As[16][132];   // transposed: As[k][m]
    __shared__ float Ws[16][132];   // transposed: Ws[k][n]

    const int t  = threadIdx.x;
    const int m0 = blockIdx.y * 128;
    const int n0 = blockIdx.x * 128;
    const int ty = t >> 4, tx = t & 15;
    const int lr = t >> 2;          // 0..63
    const int lk = (t & 3) * 4;     // 0,4,8,12

    float acc[8][8];
    #pragma unroll
    for (int i = 0; i < 8; i++)
        #pragma unroll
        for (int j = 0; j < 8; j++) acc[i][j] = 0.0f;

    const float* A0 = A + (size_t)(m0 + lr)      * HID + lk;
    const float* A1 = A + (size_t)(m0 + lr + 64) * HID + lk;
    const float* W0 = W + (size_t)(n0 + lr)      * HID + lk;
    const float* W1 = W + (size_t)(n0 + lr + 64) * HID + lk;

    for (int k0 = 0; k0 < HID; k0 += 16) {
        float4 a0 = *(const float4*)(A0 + k0);
        float4 a1 = *(const float4*)(A1 + k0);
        float4 w0 = *(const float4*)(W0 + k0);
        float4 w1 = *(const float4*)(W1 + k0);

        __syncthreads();   // previous tile's compute done
        As[lk+0][lr]    = a0.x; As[lk+1][lr]    = a0.y; As[lk+2][lr]    = a0.z; As[lk+3][lr]    = a0.w;
        As[lk+0][lr+64] = a1.x; As[lk+1][lr+64] = a1.y; As[lk+2][lr+64] = a1.z; As[lk+3][lr+64] = a1.w;
        Ws[lk+0][lr]    = w0.x; Ws[lk+1][lr]    = w0.y; Ws[lk+2][lr]    = w0.z; Ws[lk+3][lr]    = w0.w;
        Ws[lk+0][lr+64] = w1.x; Ws[lk+1][lr+64] = w1.y; Ws[lk+2][lr+64] = w1.z; Ws[lk+3][lr+64] = w1.w;
        __syncthreads();

        #pragma unroll
        for (int k = 0; k < 16; k++) {
            float4 af0 = *(const float4*)&As[k][ty*4];
            float4 af1 = *(const float4*)&As[k][ty*4 + 64];
            float4 wf0 = *(const float4*)&Ws[k][tx*4];
            float4 wf1 = *(const float4*)&Ws[k][tx*4 + 64];
            float a8[8] = {af0.x, af0.y, af0.z, af0.w, af1.x, af1.y, af1.z, af1.w};
            float w8[8] = {wf0.x, wf0.y, wf0.z, wf0.w, wf1.x, wf1.y, wf1.z, wf1.w};
            #pragma unroll
            for (int i = 0; i < 8; i++)
                #pragma unroll
                for (int j = 0; j < 8; j++)
                    acc[i][j] = fmaf(a8[i], w8[j], acc[i][j]);
        }
    }

    #pragma unroll
    for (int i = 0; i < 8; i++) {
        const int m = m0 + ((i < 4) ? (ty*4 + i) : (64 + ty*4 + i - 4));
        #pragma unroll
        for (int j = 0; j < 8; j++) {
            const int n = n0 + ((j < 4) ? (tx*4 + j) : (64 + tx*4 + j - 4));
            const float v = acc[i][j] + bias[n];
            if (MODE == 0) {
                const int b = m >> 11, s = m & (SL - 1);
                const int h = n >> 6,  d = n & 63;
                out[(((size_t)(b*NH + h)) * SL + s) * DH + d] = v;
            } else {
                out[(size_t)m * HID + n] = v;
            }
        }
    }
}

__global__ __launch_bounds__(256) void qkv_kernel(
    const float* __restrict__ x,
    const float* __restrict__ Wq, const float* __restrict__ Wk, const float* __restrict__ Wv,
    const float* __restrict__ bq, const float* __restrict__ bk, const float* __restrict__ bv)
{
    const float* W; const float* bias; float* out;
    if (blockIdx.z == 0)      { W = Wq; bias = bq; out = g_Q; }
    else if (blockIdx.z == 1) { W = Wk; bias = bk; out = g_K; }
    else                      { W = Wv; bias = bv; out = g_V; }
    gemm128<0>(x, W, bias, out);
}

__global__ __launch_bounds__(256) void oproj_kernel(
    const float* __restrict__ Wo, const float* __restrict__ bo, float* __restrict__ out)
{
    gemm128<1>(g_A, Wo, bo, out);
}

// ---------------------------------------------------------------------------
// Attention: one CTA per (b, h, 64-query tile). Streaming softmax without
// max-subtraction (all logits clamped to [-50, 50], so exp() is safe in fp32).
// ---------------------------------------------------------------------------
#define SMEM_ATTN (4 * 64 * 68 * 4 + 64 * 4)

__global__ __launch_bounds__(256) void attn_kernel(const int* __restrict__ mask)
{
    extern __shared__ float sm[];
    float* Qs = sm;              // [d][r]  64x68
    float* Ks = Qs + 64*68;      // [d][c]  64x68
    float* Vs = Ks + 64*68;      // [k][d]  64x68
    float* Ps = Vs + 64*68;      // [k][r]  64x68
    int*  msks = (int*)(Ps + 64*68);  // 64

    const int t  = threadIdx.x;
    const int ty = t >> 4, tx = t & 15;
    const int q0 = blockIdx.x * 64;
    const int h  = blockIdx.y, b = blockIdx.z;
    const size_t base = ((size_t)(b*NH + h)) * SL * DH;
    const float* Qg = g_Q + base;
    const float* Kg = g_K + base;
    const float* Vg = g_V + base;

    const int lr = t >> 2;          // 0..63
    const int lc = (t & 3) * 16;    // 0,16,32,48

    // Load Q tile transposed: Qs[d][r]
    #pragma unroll
    for (int i = 0; i < 4; i++) {
        const int d0 = lc + i*4;
        float4 v = *(const float4*)&Qg[(size_t)(q0 + lr) * DH + d0];
        Qs[(d0+0)*68 + lr] = v.x; Qs[(d0+1)*68 + lr] = v.y;
        Qs[(d0+2)*68 + lr] = v.z; Qs[(d0+3)*68 + lr] = v.w;
    }

    float o[4][4];
    #pragma unroll
    for (int i = 0; i < 4; i++)
        #pragma unroll
        for (int j = 0; j < 4; j++) o[i][j] = 0.0f;
    float den[4] = {0.f, 0.f, 0.f, 0.f};

    for (int kt = 0; kt < SL/64; kt++) {
        const int kb = kt * 64;
        float4 kv[4], vv[4];
        #pragma unroll
        for (int i = 0; i < 4; i++) {
            const int d0 = lc + i*4;
            kv[i] = *(const float4*)&Kg[(size_t)(kb + lr) * DH + d0];
            vv[i] = *(const float4*)&Vg[(size_t)(kb + lr) * DH + d0];
        }
        int mval = 0;
        if (t < 64) mval = mask[b*SL + kb + t];

        __syncthreads();   // previous tile fully consumed
        #pragma unroll
        for (int i = 0; i < 4; i++) {
            const int d0 = lc + i*4;
            Ks[(d0+0)*68 + lr] = kv[i].x; Ks[(d0+1)*68 + lr] = kv[i].y;
            Ks[(d0+2)*68 + lr] = kv[i].z; Ks[(d0+3)*68 + lr] = kv[i].w;
            *(float4*)&Vs[lr*68 + d0] = vv[i];
        }
        if (t < 64) msks[t] = mval;
        __syncthreads();

        // Scores: s[r][c] = sum_d Q[r][d] K[c][d]
        float s_[4][4];
        #pragma unroll
        for (int i = 0; i < 4; i++)
            #pragma unroll
            for (int j = 0; j < 4; j++) s_[i][j] = 0.0f;

        #pragma unroll 16
        for (int d = 0; d < 64; d++) {
            float4 qa = *(const float4*)&Qs[d*68 + ty*4];
            float4 kc = *(const float4*)&Ks[d*68 + tx*4];
            float qa4[4] = {qa.x, qa.y, qa.z, qa.w};
            float kc4[4] = {kc.x, kc.y, kc.z, kc.w};
            #pragma unroll
            for (int i = 0; i < 4; i++)
                #pragma unroll
                for (int j = 0; j < 4; j++)
                    s_[i][j] = fmaf(qa4[i], kc4[j], s_[i][j]);
        }

        // mask + clamp + exp + row partial sums
        int mk[4];
        #pragma unroll
        for (int j = 0; j < 4; j++) mk[j] = msks[tx*4 + j];

        float rs[4] = {0.f, 0.f, 0.f, 0.f};
        #pragma unroll
        for (int i = 0; i < 4; i++) {
            #pragma unroll
            for (int j = 0; j < 4; j++) {
                float sv = s_[i][j] * 0.125f;
                sv = fminf(fmaxf(sv, -50.0f), 50.0f);
                sv = (mk[j] != 0) ? sv : -50.0f;
                float p = __expf(sv);
                s_[i][j] = p;
                rs[i] += p;
            }
        }
        // reduce across the 16 threads sharing the same rows
        #pragma unroll
        for (int i = 0; i < 4; i++) {
            float r = rs[i];
            r += __shfl_xor_sync(0xffffffffu, r, 1, 16);
            r += __shfl_xor_sync(0xffffffffu, r, 2, 16);
            r += __shfl_xor_sync(0xffffffffu, r, 4, 16);
            r += __shfl_xor_sync(0xffffffffu, r, 8, 16);
            den[i] += r;
        }

        // stash P transposed: Ps[k][r]
        #pragma unroll
        for (int j = 0; j < 4; j++)
            #pragma unroll
            for (int i = 0; i < 4; i++)
                Ps[(tx*4 + j)*68 + ty*4 + i] = s_[i][j];
        __syncthreads();

        // O += P * V
        #pragma unroll 16
        for (int k = 0; k < 64; k++) {
            float4 pa = *(const float4*)&Ps[k*68 + ty*4];
            float4 vb = *(const float4*)&Vs[k*68 + tx*4];
            float pa4[4] = {pa.x, pa.y, pa.z, pa.w};
            float vb4[4] = {vb.x, vb.y, vb.z, vb.w};
            #pragma unroll
            for (int i = 0; i < 4; i++)
                #pragma unroll
                for (int j = 0; j < 4; j++)
                    o[i][j] = fmaf(pa4[i], vb4[j], o[i][j]);
        }
    }

    // normalize and store into [B,S,HID]
    #pragma unroll
    for (int i = 0; i < 4; i++) {
        const float inv = 1.0f / den[i];
        float4 ov;
        ov.x = o[i][0] * inv; ov.y = o[i][1] * inv;
        ov.z = o[i][2] * inv; ov.w = o[i][3] * inv;
        *(float4*)&g_A[((size_t)(b*SL + q0 + ty*4 + i)) * HID + h*DH + tx*4] = ov;
    }
}

// ---------------------------------------------------------------------------
extern "C" void kernel_launch(void* const* d_in, const int* in_sizes, int n_in,
                              void* d_out, int out_size)
{
    const float* x    = (const float*)d_in[0];
    const int*   mask = (const int*)  d_in[1];
    const float* Wq   = (const float*)d_in[2];
    const float* bq   = (const float*)d_in[3];
    const float* Wk   = (const float*)d_in[4];
    const float* bk   = (const float*)d_in[5];
    const float* Wv   = (const float*)d_in[6];
    const float* bv   = (const float*)d_in[7];
    const float* Wo   = (const float*)d_in[8];
    const float* bo   = (const float*)d_in[9];
    float* out = (float*)d_out;

    cudaFuncSetAttribute(attn_kernel, cudaFuncAttributeMaxDynamicSharedMemorySize, SMEM_ATTN);

    dim3 gqkv(HID/128, MROWS/128, 3);
    qkv_kernel<<<gqkv, 256>>>(x, Wq, Wk, Wv, bq, bk, bv);

    dim3 gattn(SL/64, NH, NB);
    attn_kernel<<<gattn, 256, SMEM_ATTN>>>(mask);

    dim3 go(HID/128, MROWS/128, 1);
    oproj_kernel<<<go, 256>>>(Wo, bo, out);
}

// round 3
// speedup vs baseline: 2.3562x; 2.3562x over previous
#include <cuda_runtime.h>
#include <cuda_bf16.h>
#include <cstdint>

#define NH   16
#define DH   64
#define HID  1024
#define NB   4
#define SL   2048
#define MROWS (NB*SL)   // 8192

// Scratch (device globals: allocation-free)
__device__ float g_Q[(size_t)NB*NH*SL*DH];   // [B,H,S,D]
__device__ float g_K[(size_t)NB*NH*SL*DH];
__device__ float g_V[(size_t)NB*NH*SL*DH];
__device__ float g_A[(size_t)NB*SL*HID];     // [B,S,HID]

// ---------------------------------------------------------------------------
// MMA / ldmatrix helpers
// ---------------------------------------------------------------------------
__device__ __forceinline__ uint32_t smem_u32(const void* p) {
    return (uint32_t)__cvta_generic_to_shared(p);
}
__device__ __forceinline__ void ldm4(uint32_t r[4], uint32_t a) {
    asm volatile("ldmatrix.sync.aligned.m8n8.x4.shared.b16 {%0,%1,%2,%3},[%4];"
        : "=r"(r[0]), "=r"(r[1]), "=r"(r[2]), "=r"(r[3]) : "r"(a));
}
__device__ __forceinline__ void ldm2(uint32_t r[2], uint32_t a) {
    asm volatile("ldmatrix.sync.aligned.m8n8.x2.shared.b16 {%0,%1},[%2];"
        : "=r"(r[0]), "=r"(r[1]) : "r"(a));
}
__device__ __forceinline__ void ldm2t(uint32_t r[2], uint32_t a) {
    asm volatile("ldmatrix.sync.aligned.m8n8.x2.trans.shared.b16 {%0,%1},[%2];"
        : "=r"(r[0]), "=r"(r[1]) : "r"(a));
}
__device__ __forceinline__ void mma_bf(float c[4], const uint32_t a[4], const uint32_t b[2]) {
    asm volatile("mma.sync.aligned.m16n8k16.row.col.f32.bf16.bf16.f32 "
                 "{%0,%1,%2,%3},{%4,%5,%6,%7},{%8,%9},{%0,%1,%2,%3};"
        : "+f"(c[0]), "+f"(c[1]), "+f"(c[2]), "+f"(c[3])
        : "r"(a[0]), "r"(a[1]), "r"(a[2]), "r"(a[3]), "r"(b[0]), "r"(b[1]));
}
__device__ __forceinline__ uint32_t pk(float a, float b) {
    __nv_bfloat162 t = __floats2bfloat162_rn(a, b);
    return *reinterpret_cast<uint32_t*>(&t);
}
__device__ __forceinline__ float bfhi(float x) {
    return __bfloat162float(__float2bfloat16_rn(x));
}
// split 4 floats into packed hi pair-words and lo pair-words
__device__ __forceinline__ void split4(const float4 v, uint32_t hi[2], uint32_t lo[2]) {
    float h0 = bfhi(v.x), h1 = bfhi(v.y), h2 = bfhi(v.z), h3 = bfhi(v.w);
    hi[0] = pk(h0, h1); hi[1] = pk(h2, h3);
    lo[0] = pk(v.x - h0, v.y - h1); lo[1] = pk(v.z - h2, v.w - h3);
}

// ---------------------------------------------------------------------------
// bf16x3 tensor-core GEMM: Y[m][n] = sum_k A[m][k]*W[n][k] + bias[n]
// CTA 128x128, 8 warps (2x4), warp tile 64x32; k-chunk 32.
// MODE 0: write [B,H,S,D] split-head. MODE 1: write flat [M][HID].
// ---------------------------------------------------------------------------
template<int MODE>
__device__ __forceinline__ void gemm_tc(const float* __restrict__ A,
                                        const float* __restrict__ W,
                                        const float* __restrict__ bias,
                                        float* __restrict__ out)
{
    __shared__ __align__(16) __nv_bfloat16 Ah[128*40], Al[128*40], Wh[128*40], Wl[128*40];

    const int t = threadIdx.x, lane = t & 31, wid = t >> 5;
    const int wy = wid >> 2, wx = wid & 3;
    const int m0 = blockIdx.y * 128, n0 = blockIdx.x * 128;
    const int gid = lane >> 2, tig = lane & 3;

    float c[4][4][4];
    #pragma unroll
    for (int mi = 0; mi < 4; mi++)
        #pragma unroll
        for (int ni = 0; ni < 4; ni++)
            #pragma unroll
            for (int r = 0; r < 4; r++) c[mi][ni][r] = 0.0f;

    const int lrow = t >> 1, lcb = (t & 1) * 16;
    const float* Ap = A + (size_t)(m0 + lrow) * HID + lcb;
    const float* Wp = W + (size_t)(n0 + lrow) * HID + lcb;

    const uint32_t sAh = smem_u32(Ah), sAl = smem_u32(Al);
    const uint32_t sWh = smem_u32(Wh), sWl = smem_u32(Wl);

    for (int k0 = 0; k0 < HID; k0 += 32) {
        float4 av[4], wv[4];
        #pragma unroll
        for (int j = 0; j < 4; j++) {
            av[j] = *(const float4*)(Ap + k0 + j*4);
            wv[j] = *(const float4*)(Wp + k0 + j*4);
        }
        __syncthreads();
        #pragma unroll
        for (int j = 0; j < 4; j++) {
            uint32_t hi[2], lo[2];
            const int idx = lrow*40 + lcb + j*4;
            split4(av[j], hi, lo);
            *(uint32_t*)&Ah[idx]   = hi[0]; *(uint32_t*)&Ah[idx+2] = hi[1];
            *(uint32_t*)&Al[idx]   = lo[0]; *(uint32_t*)&Al[idx+2] = lo[1];
            split4(wv[j], hi, lo);
            *(uint32_t*)&Wh[idx]   = hi[0]; *(uint32_t*)&Wh[idx+2] = hi[1];
            *(uint32_t*)&Wl[idx]   = lo[0]; *(uint32_t*)&Wl[idx+2] = lo[1];
        }
        __syncthreads();

        #pragma unroll
        for (int ks = 0; ks < 32; ks += 16) {
            uint32_t bh[4][2], bl[4][2];
            #pragma unroll
            for (int ni = 0; ni < 4; ni++) {
                const uint32_t off = (uint32_t)(((wx*32 + ni*8 + (lane & 7))*40 + ks)*2
                                     + ((lane >> 3) & 1)*16);
                ldm2(bh[ni], sWh + off);
                ldm2(bl[ni], sWl + off);
            }
            #pragma unroll
            for (int mi = 0; mi < 4; mi++) {
                const uint32_t off = (uint32_t)(((wy*64 + mi*16 + (lane & 15))*40 + ks)*2
                                     + (lane >> 4)*16);
                uint32_t ah[4], al[4];
                ldm4(ah, sAh + off);
                ldm4(al, sAl + off);
                #pragma unroll
                for (int ni = 0; ni < 4; ni++) {
                    mma_bf(c[mi][ni], ah, bh[ni]);
                    mma_bf(c[mi][ni], ah, bl[ni]);
                    mma_bf(c[mi][ni], al, bh[ni]);
                }
            }
        }
    }

    // epilogue: fragment layout c0:(gid,2t) c1:(gid,2t+1) c2:(gid+8,2t) c3:(gid+8,2t+1)
    #pragma unroll
    for (int mi = 0; mi < 4; mi++) {
        const int r0 = m0 + wy*64 + mi*16 + gid;
        #pragma unroll
        for (int ni = 0; ni < 4; ni++) {
            const int col = n0 + wx*32 + ni*8 + 2*tig;
            const float b0 = bias[col], b1 = bias[col+1];
            float2 v0 = make_float2(c[mi][ni][0] + b0, c[mi][ni][1] + b1);
            float2 v1 = make_float2(c[mi][ni][2] + b0, c[mi][ni][3] + b1);
            if (MODE == 0) {
                const int hh = col >> 6, d = col & 63;
                const int b_ = r0 >> 11, s0 = r0 & (SL-1);
                float* p0 = &out[(((size_t)(b_*NH + hh))*SL + s0)*DH + d];
                *(float2*)p0 = v0;
                const int b1_ = (r0+8) >> 11, s1 = (r0+8) & (SL-1);
                float* p1 = &out[(((size_t)(b1_*NH + hh))*SL + s1)*DH + d];
                *(float2*)p1 = v1;
            } else {
                *(float2*)&out[(size_t)r0*HID + col]     = v0;
                *(float2*)&out[(size_t)(r0+8)*HID + col] = v1;
            }
        }
    }
}

__global__ __launch_bounds__(256) void qkv_kernel(
    const float* __restrict__ x,
    const float* __restrict__ Wq, const float* __restrict__ Wk, const float* __restrict__ Wv,
    const float* __restrict__ bq, const float* __restrict__ bk, const float* __restrict__ bv)
{
    const float* W; const float* bias; float* out;
    if (blockIdx.z == 0)      { W = Wq; bias = bq; out = g_Q; }
    else if (blockIdx.z == 1) { W = Wk; bias = bk; out = g_K; }
    else                      { W = Wv; bias = bv; out = g_V; }
    gemm_tc<0>(x, W, bias, out);
}

__global__ __launch_bounds__(256) void oproj_kernel(
    const float* __restrict__ Wo, const float* __restrict__ bo, float* __restrict__ out)
{
    gemm_tc<1>(g_A, Wo, bo, out);
}

// ---------------------------------------------------------------------------
// Attention, bf16x3 tensor cores. CTA: 128 q-rows x 1 head. 512 threads.
// Warp grid 4x4 over (128 q, 64 k/d): warp tile 32x16.
// Streaming softmax without rescaling (logits clamped to [-50,50]).
// ---------------------------------------------------------------------------
// smem layout (bf16 elems unless noted):
//   Qh 128*72 | Ql | Kh 64*72 | Kl | Vh | Vl | Ph 128*72 | Pl | denp 4*128 f32 | msk 64 i32
#define ATT_QH   0
#define ATT_QL   (128*72)
#define ATT_KH   (2*128*72)
#define ATT_KL   (2*128*72 + 64*72)
#define ATT_VH   (2*128*72 + 2*64*72)
#define ATT_VL   (2*128*72 + 3*64*72)
#define ATT_PH   (2*128*72 + 4*64*72)
#define ATT_PL   (3*128*72 + 4*64*72)
#define ATT_BF_TOT (4*128*72 + 4*64*72)            // bf16 elems
#define ATT_DENP (ATT_BF_TOT*2)                    // byte offset
#define ATT_MSK  (ATT_DENP + 4*128*4)
#define ATT_SMEM (ATT_MSK + 64*4)

__global__ __launch_bounds__(512) void attn_tc(const int* __restrict__ mask)
{
    extern __shared__ __align__(16) unsigned char smraw[];
    __nv_bfloat16* bfm  = (__nv_bfloat16*)smraw;
    float* denp = (float*)(smraw + ATT_DENP);
    int*   msk  = (int*)  (smraw + ATT_MSK);

    const int t = threadIdx.x, lane = t & 31, wid = t >> 5;
    const int wm = wid >> 2, wn = wid & 3;
    const int gid = lane >> 2, tig = lane & 3;
    const int q0 = blockIdx.x * 128, h = blockIdx.y, b = blockIdx.z;
    const size_t base = ((size_t)(b*NH + h)) * SL * DH;
    const float* Qg = g_Q + base;
    const float* Kg = g_K + base;
    const float* Vg = g_V + base;

    const uint32_t sQh = smem_u32(bfm + ATT_QH), sQl = smem_u32(bfm + ATT_QL);
    const uint32_t sKh = smem_u32(bfm + ATT_KH), sKl = smem_u32(bfm + ATT_KL);
    const uint32_t sVh = smem_u32(bfm + ATT_VH), sVl = smem_u32(bfm + ATT_VL);
    const uint32_t sPh = smem_u32(bfm + ATT_PH), sPl = smem_u32(bfm + ATT_PL);

    // stage Q (128x64) as hi/lo
    {
        const int row = t >> 2, cb = (t & 3) * 16;
        #pragma unroll
        for (int j = 0; j < 4; j++) {
            float4 v = *(const float4*)&Qg[(size_t)(q0 + row)*DH + cb + j*4];
            uint32_t hi[2], lo[2];
            split4(v, hi, lo);
            const int idx = row*72 + cb + j*4;
            *(uint32_t*)&bfm[ATT_QH + idx]   = hi[0]; *(uint32_t*)&bfm[ATT_QH + idx+2] = hi[1];
            *(uint32_t*)&bfm[ATT_QL + idx]   = lo[0]; *(uint32_t*)&bfm[ATT_QL + idx+2] = lo[1];
        }
    }
    if (t < 512) denp[t] = 0.0f;   // 4*128

    float o[2][2][4];
    #pragma unroll
    for (int mi = 0; mi < 2; mi++)
        #pragma unroll
        for (int ni = 0; ni < 2; ni++)
            #pragma unroll
            for (int r = 0; r < 4; r++) o[mi][ni][r] = 0.0f;
    float den_r[4] = {0.f, 0.f, 0.f, 0.f};

    const int krow = t >> 3, kcb = (t & 7) * 8;

    for (int kt = 0; kt < SL/64; kt++) {
        const int kb = kt * 64;
        float4 kv0 = *(const float4*)&Kg[(size_t)(kb + krow)*DH + kcb];
        float4 kv1 = *(const float4*)&Kg[(size_t)(kb + krow)*DH + kcb + 4];
        float4 vv0 = *(const float4*)&Vg[(size_t)(kb + krow)*DH + kcb];
        float4 vv1 = *(const float4*)&Vg[(size_t)(kb + krow)*DH + kcb + 4];
        int mval = 0;
        if (t < 64) mval = mask[b*SL + kb + t];

        __syncthreads();   // prior tile fully consumed (PV done)
        {
            uint32_t hi[2], lo[2];
            const int idx = krow*72 + kcb;
            split4(kv0, hi, lo);
            *(uint32_t*)&bfm[ATT_KH + idx]   = hi[0]; *(uint32_t*)&bfm[ATT_KH + idx+2] = hi[1];
            *(uint32_t*)&bfm[ATT_KL + idx]   = lo[0]; *(uint32_t*)&bfm[ATT_KL + idx+2] = lo[1];
            split4(kv1, hi, lo);
            *(uint32_t*)&bfm[ATT_KH + idx+4] = hi[0]; *(uint32_t*)&bfm[ATT_KH + idx+6] = hi[1];
            *(uint32_t*)&bfm[ATT_KL + idx+4] = lo[0]; *(uint32_t*)&bfm[ATT_KL + idx+6] = lo[1];
            split4(vv0, hi, lo);
            *(uint32_t*)&bfm[ATT_VH + idx]   = hi[0]; *(uint32_t*)&bfm[ATT_VH + idx+2] = hi[1];
            *(uint32_t*)&bfm[ATT_VL + idx]   = lo[0]; *(uint32_t*)&bfm[ATT_VL + idx+2] = lo[1];
            split4(vv1, hi, lo);
            *(uint32_t*)&bfm[ATT_VH + idx+4] = hi[0]; *(uint32_t*)&bfm[ATT_VH + idx+6] = hi[1];
            *(uint32_t*)&bfm[ATT_VL + idx+4] = lo[0]; *(uint32_t*)&bfm[ATT_VL + idx+6] = lo[1];
        }
        if (t < 64) msk[t] = mval;
        __syncthreads();

        // ---- QK: S = Q K^T (per-warp 32x16 tile) ----
        float cS[2][2][4];
        #pragma unroll
        for (int mi = 0; mi < 2; mi++)
            #pragma unroll
            for (int ni = 0; ni < 2; ni++)
                #pragma unroll
                for (int r = 0; r < 4; r++) cS[mi][ni][r] = 0.0f;

        #pragma unroll
        for (int ks = 0; ks < 64; ks += 16) {
            uint32_t bh[2][2], bl[2][2];
            #pragma unroll
            for (int ni = 0; ni < 2; ni++) {
                const uint32_t off = (uint32_t)(((wn*16 + ni*8 + (lane & 7))*72 + ks)*2
                                     + ((lane >> 3) & 1)*16);
                ldm2(bh[ni], sKh + off);
                ldm2(bl[ni], sKl + off);
            }
            #pragma unroll
            for (int mi = 0; mi < 2; mi++) {
                const uint32_t off = (uint32_t)(((wm*32 + mi*16 + (lane & 15))*72 + ks)*2
                                     + (lane >> 4)*16);
                uint32_t ah[4], al[4];
                ldm4(ah, sQh + off);
                ldm4(al, sQl + off);
                #pragma unroll
                for (int ni = 0; ni < 2; ni++) {
                    mma_bf(cS[mi][ni], ah, bh[ni]);
                    mma_bf(cS[mi][ni], ah, bl[ni]);
                    mma_bf(cS[mi][ni], al, bh[ni]);
                }
            }
        }

        // ---- softmax numerator: scale/clamp/mask/exp in registers ----
        float rs[4] = {0.f, 0.f, 0.f, 0.f};
        #pragma unroll
        for (int mi = 0; mi < 2; mi++) {
            const int r0 = wm*32 + mi*16 + gid;
            #pragma unroll
            for (int ni = 0; ni < 2; ni++) {
                const int colb = wn*16 + ni*8 + 2*tig;
                const int mA = msk[colb], mB = msk[colb+1];
                float p[4];
                #pragma unroll
                for (int r = 0; r < 4; r++) {
                    float s = cS[mi][ni][r] * 0.125f;
                    s = fminf(fmaxf(s, -50.0f), 50.0f);
                    const int mm = (r & 1) ? mB : mA;
                    s = mm ? s : -50.0f;
                    p[r] = __expf(s);
                }
                rs[mi*2+0] += p[0] + p[1];
                rs[mi*2+1] += p[2] + p[3];
                const float h0 = bfhi(p[0]), h1 = bfhi(p[1]);
                const float h2 = bfhi(p[2]), h3 = bfhi(p[3]);
                const int i0 = r0*72 + colb, i1 = (r0+8)*72 + colb;
                *(uint32_t*)&bfm[ATT_PH + i0] = pk(h0, h1);
                *(uint32_t*)&bfm[ATT_PL + i0] = pk(p[0]-h0, p[1]-h1);
                *(uint32_t*)&bfm[ATT_PH + i1] = pk(h2, h3);
                *(uint32_t*)&bfm[ATT_PL + i1] = pk(p[2]-h2, p[3]-h3);
            }
        }
        #pragma unroll
        for (int i = 0; i < 4; i++) {
            float r = rs[i];
            r += __shfl_xor_sync(0xffffffffu, r, 1, 4);
            r += __shfl_xor_sync(0xffffffffu, r, 2, 4);
            den_r[i] += r;
        }
        __syncthreads();   // P visible to all warps

        // ---- PV: O += P V ----
        #pragma unroll
        for (int ks = 0; ks < 64; ks += 16) {
            uint32_t bh[2][2], bl[2][2];
            #pragma unroll
            for (int ni = 0; ni < 2; ni++) {
                const uint32_t off = (uint32_t)(((ks + (lane & 7) + ((lane >> 3) & 1)*8)*72
                                     + (wn*16 + ni*8))*2);
                ldm2t(bh[ni], sVh + off);
                ldm2t(bl[ni], sVl + off);
            }
            #pragma unroll
            for (int mi = 0; mi < 2; mi++) {
                const uint32_t off = (uint32_t)(((wm*32 + mi*16 + (lane & 15))*72 + ks)*2
                                     + (lane >> 4)*16);
                uint32_t ah[4], al[4];
                ldm4(ah, sPh + off);
                ldm4(al, sPl + off);
                #pragma unroll
                for (int ni = 0; ni < 2; ni++) {
                    mma_bf(o[mi][ni], ah, bh[ni]);
                    mma_bf(o[mi][ni], ah, bl[ni]);
                    mma_bf(o[mi][ni], al, bh[ni]);
                }
            }
        }
    }

    // publish row-sum partials (rows wm*32 + gid + {0,8,16,24}, per wn)
    if (tig == 0) {
        denp[wn*128 + wm*32 + gid]      = den_r[0];
        denp[wn*128 + wm*32 + gid + 8]  = den_r[1];
        denp[wn*128 + wm*32 + gid + 16] = den_r[2];
        denp[wn*128 + wm*32 + gid + 24] = den_r[3];
    }
    __syncthreads();

    // epilogue: normalize and write [B,S,HID]
    #pragma unroll
    for (int mi = 0; mi < 2; mi++) {
        const int r0 = wm*32 + mi*16 + gid;
        const float d0 = denp[r0] + denp[128 + r0] + denp[256 + r0] + denp[384 + r0];
        const int r1 = r0 + 8;
        const float d1 = denp[r1] + denp[128 + r1] + denp[256 + r1] + denp[384 + r1];
        const float inv0 = 1.0f / d0, inv1 = 1.0f / d1;
        #pragma unroll
        for (int ni = 0; ni < 2; ni++) {
            const int col = wn*16 + ni*8 + 2*tig;
            float2 v0 = make_float2(o[mi][ni][0]*inv0, o[mi][ni][1]*inv0);
            float2 v1 = make_float2(o[mi][ni][2]*inv1, o[mi][ni][3]*inv1);
            *(float2*)&g_A[((size_t)(b*SL + q0 + r0))*HID + h*DH + col] = v0;
            *(float2*)&g_A[((size_t)(b*SL + q0 + r1))*HID + h*DH + col] = v1;
        }
    }
}

// ---------------------------------------------------------------------------
extern "C" void kernel_launch(void* const* d_in, const int* in_sizes, int n_in,
                              void* d_out, int out_size)
{
    const float* x    = (const float*)d_in[0];
    const int*   mask = (const int*)  d_in[1];
    const float* Wq   = (const float*)d_in[2];
    const float* bq   = (const float*)d_in[3];
    const float* Wk   = (const float*)d_in[4];
    const float* bk   = (const float*)d_in[5];
    const float* Wv   = (const float*)d_in[6];
    const float* bv   = (const float*)d_in[7];
    const float* Wo   = (const float*)d_in[8];
    const float* bo   = (const float*)d_in[9];
    float* out = (float*)d_out;

    cudaFuncSetAttribute(attn_tc, cudaFuncAttributeMaxDynamicSharedMemorySize, ATT_SMEM);

    dim3 gqkv(HID/128, MROWS/128, 3);
    qkv_kernel<<<gqkv, 256>>>(x, Wq, Wk, Wv, bq, bk, bv);

    dim3 gattn(SL/128, NH, NB);
    attn_tc<<<gattn, 512, ATT_SMEM>>>(mask);

    dim3 go(HID/128, MROWS/128, 1);
    oproj_kernel<<<go, 256>>>(Wo, bo, out);
}

// round 6
// speedup vs baseline: 2.9728x; 1.2617x over previous
#include <cuda_runtime.h>
#include <cuda_bf16.h>
#include <cstdint>

#define NH   16
#define DH   64
#define HID  1024
#define NB   4
#define SL   2048
#define MROWS (NB*SL)                 // 8192
#define QKVN ((size_t)NB*NH*SL*DH)    // 8.4M

// ---------------------------------------------------------------------------
// Global scratch (allocation-free): pre-split bf16 hi/lo operands
// ---------------------------------------------------------------------------
__device__ __nv_bfloat16 g_xh[(size_t)MROWS*HID], g_xl[(size_t)MROWS*HID];
__device__ __nv_bfloat16 g_Wh[4][(size_t)HID*HID], g_Wl[4][(size_t)HID*HID];
__device__ __nv_bfloat16 g_Qh[QKVN], g_Ql[QKVN];
__device__ __nv_bfloat16 g_Kh[QKVN], g_Kl[QKVN];
__device__ __nv_bfloat16 g_Vh[QKVN], g_Vl[QKVN];
__device__ __nv_bfloat16 g_Ah[(size_t)MROWS*HID], g_Al[(size_t)MROWS*HID];

// ---------------------------------------------------------------------------
// helpers
// ---------------------------------------------------------------------------
__device__ __forceinline__ uint32_t smem_u32(const void* p) {
    return (uint32_t)__cvta_generic_to_shared(p);
}
__device__ __forceinline__ void ldm4(uint32_t r[4], uint32_t a) {
    asm volatile("ldmatrix.sync.aligned.m8n8.x4.shared.b16 {%0,%1,%2,%3},[%4];"
        : "=r"(r[0]), "=r"(r[1]), "=r"(r[2]), "=r"(r[3]) : "r"(a));
}
__device__ __forceinline__ void ldm2(uint32_t r[2], uint32_t a) {
    asm volatile("ldmatrix.sync.aligned.m8n8.x2.shared.b16 {%0,%1},[%2];"
        : "=r"(r[0]), "=r"(r[1]) : "r"(a));
}
__device__ __forceinline__ void ldm2t(uint32_t r[2], uint32_t a) {
    asm volatile("ldmatrix.sync.aligned.m8n8.x2.trans.shared.b16 {%0,%1},[%2];"
        : "=r"(r[0]), "=r"(r[1]) : "r"(a));
}
__device__ __forceinline__ void mma_bf(float c[4], const uint32_t a[4], const uint32_t b[2]) {
    asm volatile("mma.sync.aligned.m16n8k16.row.col.f32.bf16.bf16.f32 "
                 "{%0,%1,%2,%3},{%4,%5,%6,%7},{%8,%9},{%0,%1,%2,%3};"
        : "+f"(c[0]), "+f"(c[1]), "+f"(c[2]), "+f"(c[3])
        : "r"(a[0]), "r"(a[1]), "r"(a[2]), "r"(a[3]), "r"(b[0]), "r"(b[1]));
}
__device__ __forceinline__ void cp16(uint32_t dst, const void* src) {
    asm volatile("cp.async.cg.shared.global [%0], [%1], 16;" :: "r"(dst), "l"(src));
}
#define CP_COMMIT asm volatile("cp.async.commit_group;" ::: "memory")
#define CP_WAIT1  asm volatile("cp.async.wait_group 1;" ::: "memory")
#define CP_WAIT0  asm volatile("cp.async.wait_group 0;" ::: "memory")

__device__ __forceinline__ uint32_t pk(float a, float b) {
    __nv_bfloat162 t = __floats2bfloat162_rn(a, b);
    return *reinterpret_cast<uint32_t*>(&t);
}
__device__ __forceinline__ float bfhi(float x) {
    return __bfloat162float(__float2bfloat16_rn(x));
}
__device__ __forceinline__ void split4(const float4 v, uint32_t hi[2], uint32_t lo[2]) {
    float h0 = bfhi(v.x), h1 = bfhi(v.y), h2 = bfhi(v.z), h3 = bfhi(v.w);
    hi[0] = pk(h0, h1); hi[1] = pk(h2, h3);
    lo[0] = pk(v.x - h0, v.y - h1); lo[1] = pk(v.z - h2, v.w - h3);
}

// ---------------------------------------------------------------------------
// Prep: split fp32 -> bf16 hi/lo (once per element)
// ---------------------------------------------------------------------------
__global__ void split_x_kernel(const float* __restrict__ src)
{
    const size_t n4 = (size_t)MROWS * HID / 4;
    for (size_t i = (size_t)blockIdx.x * blockDim.x + threadIdx.x; i < n4;
         i += (size_t)gridDim.x * blockDim.x) {
        float4 v = ((const float4*)src)[i];
        uint32_t hi[2], lo[2];
        split4(v, hi, lo);
        ((uint2*)g_xh)[i] = make_uint2(hi[0], hi[1]);
        ((uint2*)g_xl)[i] = make_uint2(lo[0], lo[1]);
    }
}

__global__ void split_w_kernel(const float* __restrict__ Wq, const float* __restrict__ Wk,
                               const float* __restrict__ Wv, const float* __restrict__ Wo)
{
    const int z = blockIdx.y;
    const float* src = (z == 0) ? Wq : (z == 1) ? Wk : (z == 2) ? Wv : Wo;
    const size_t n4 = (size_t)HID * HID / 4;
    for (size_t i = (size_t)blockIdx.x * blockDim.x + threadIdx.x; i < n4;
         i += (size_t)gridDim.x * blockDim.x) {
        float4 v = ((const float4*)src)[i];
        uint32_t hi[2], lo[2];
        split4(v, hi, lo);
        ((uint2*)g_Wh[z])[i] = make_uint2(hi[0], hi[1]);
        ((uint2*)g_Wl[z])[i] = make_uint2(lo[0], lo[1]);
    }
}

// ---------------------------------------------------------------------------
// bf16x3 GEMM with cp.async staging of pre-split operands.
// CTA 128x128, 256 threads (8 warps 2x4, warp tile 64x32), k-chunk 32,
// 2-stage cp.async pipeline. Smem rows padded to 40 bf16 (80B) - conflict free.
// MODE 0: split-head [B,H,S,D] hi/lo bf16 output. MODE 1: flat fp32 output.
// ---------------------------------------------------------------------------
#define GS_ARR   10240      // 128 rows * 80B
#define GS_STAGE (4*GS_ARR) // Ah,Al,Bh,Bl
#define GEMM_SMEM (2*GS_STAGE)

template<int MODE>
__device__ __forceinline__ void gemm_ca(
    const __nv_bfloat16* __restrict__ Ah_g, const __nv_bfloat16* __restrict__ Al_g,
    const __nv_bfloat16* __restrict__ Bh_g, const __nv_bfloat16* __restrict__ Bl_g,
    const float* __restrict__ bias,
    float* __restrict__ out, __nv_bfloat16* __restrict__ outh, __nv_bfloat16* __restrict__ outl)
{
    extern __shared__ __align__(16) unsigned char sm[];
    const int t = threadIdx.x, lane = t & 31, wid = t >> 5;
    const int wy = wid >> 2, wx = wid & 3;
    const int m0 = blockIdx.y * 128, n0 = blockIdx.x * 128;
    const uint32_t smb = smem_u32(sm);

    float acc[4][4][4];
    #pragma unroll
    for (int mi = 0; mi < 4; mi++)
        #pragma unroll
        for (int ni = 0; ni < 4; ni++)
            #pragma unroll
            for (int r = 0; r < 4; r++) acc[mi][ni][r] = 0.0f;

    auto prefetch = [&](int stage, int c) {
        const int k0 = c * 32;
        const uint32_t stb = smb + stage * GS_STAGE;
        #pragma unroll
        for (int i = 0; i < 8; i++) {
            const int g = t + i * 256;
            const int arr = g >> 9, rem = g & 511;
            const int r = rem >> 2, cg = rem & 3;
            const __nv_bfloat16* src =
                (arr == 0) ? Ah_g + (size_t)(m0 + r) * HID + k0 + cg * 8 :
                (arr == 1) ? Al_g + (size_t)(m0 + r) * HID + k0 + cg * 8 :
                (arr == 2) ? Bh_g + (size_t)(n0 + r) * HID + k0 + cg * 8 :
                             Bl_g + (size_t)(n0 + r) * HID + k0 + cg * 8;
            cp16(stb + arr * GS_ARR + r * 80 + cg * 16, src);
        }
        CP_COMMIT;
    };

    prefetch(0, 0);
    prefetch(1, 1);

    for (int c = 0; c < 32; c++) {
        if (c < 30) { CP_WAIT1; } else { CP_WAIT0; }
        __syncthreads();
        const uint32_t stb = smb + (c & 1) * GS_STAGE;
        const uint32_t sAh = stb, sAl = stb + GS_ARR;
        const uint32_t sBh = stb + 2*GS_ARR, sBl = stb + 3*GS_ARR;
        #pragma unroll
        for (int ks = 0; ks < 32; ks += 16) {
            uint32_t bh[4][2], bl[4][2];
            #pragma unroll
            for (int ni = 0; ni < 4; ni++) {
                const uint32_t off = (uint32_t)((wx*32 + ni*8 + (lane & 7)) * 80
                                     + ks*2 + ((lane >> 3) & 1) * 16);
                ldm2(bh[ni], sBh + off);
                ldm2(bl[ni], sBl + off);
            }
            #pragma unroll
            for (int mi = 0; mi < 4; mi++) {
                const uint32_t off = (uint32_t)((wy*64 + mi*16 + (lane & 15)) * 80
                                     + ks*2 + (lane >> 4) * 16);
                uint32_t ah[4], al_[4];
                ldm4(ah, sAh + off);
                ldm4(al_, sAl + off);
                #pragma unroll
                for (int ni = 0; ni < 4; ni++) {
                    mma_bf(acc[mi][ni], ah, bh[ni]);
                    mma_bf(acc[mi][ni], ah, bl[ni]);
                    mma_bf(acc[mi][ni], al_, bh[ni]);
                }
            }
        }
        __syncthreads();
        if (c + 2 < 32) prefetch(c & 1, c + 2);
    }

    const int gid = lane >> 2, tig = lane & 3;
    #pragma unroll
    for (int mi = 0; mi < 4; mi++) {
        const int r0 = m0 + wy*64 + mi*16 + gid;
        #pragma unroll
        for (int ni = 0; ni < 4; ni++) {
            const int col = n0 + wx*32 + ni*8 + 2*tig;
            const float b0 = bias[col], b1 = bias[col+1];
            const float v0 = acc[mi][ni][0] + b0, v1 = acc[mi][ni][1] + b1;
            const float v2 = acc[mi][ni][2] + b0, v3 = acc[mi][ni][3] + b1;
            if (MODE == 0) {
                const int h_ = col >> 6, d = col & 63;
                {
                    const int b_ = r0 >> 11, s_ = r0 & (SL-1);
                    const size_t off = (((size_t)(b_*NH + h_))*SL + s_)*DH + d;
                    const float h0f = bfhi(v0), h1f = bfhi(v1);
                    *(uint32_t*)&outh[off] = pk(h0f, h1f);
                    *(uint32_t*)&outl[off] = pk(v0 - h0f, v1 - h1f);
                }
                {
                    const int r1 = r0 + 8;
                    const int b_ = r1 >> 11, s_ = r1 & (SL-1);
                    const size_t off = (((size_t)(b_*NH + h_))*SL + s_)*DH + d;
                    const float h0f = bfhi(v2), h1f = bfhi(v3);
                    *(uint32_t*)&outh[off] = pk(h0f, h1f);
                    *(uint32_t*)&outl[off] = pk(v2 - h0f, v3 - h1f);
                }
            } else {
                *(float2*)&out[(size_t)r0*HID + col]     = make_float2(v0, v1);
                *(float2*)&out[(size_t)(r0+8)*HID + col] = make_float2(v2, v3);
            }
        }
    }
}

__global__ __launch_bounds__(256, 2) void qkv_ca(
    const float* __restrict__ bq, const float* __restrict__ bk, const float* __restrict__ bv)
{
    const int z = blockIdx.z;
    const float* bias = (z == 0) ? bq : (z == 1) ? bk : bv;
    __nv_bfloat16 *oh, *ol;
    if (z == 0)      { oh = g_Qh; ol = g_Ql; }
    else if (z == 1) { oh = g_Kh; ol = g_Kl; }
    else             { oh = g_Vh; ol = g_Vl; }
    gemm_ca<0>(g_xh, g_xl, g_Wh[z], g_Wl[z], bias, nullptr, oh, ol);
}

__global__ __launch_bounds__(256, 2) void oproj_ca(
    const float* __restrict__ bo, float* __restrict__ out)
{
    gemm_ca<1>(g_Ah, g_Al, g_Wh[3], g_Wl[3], bo, out, nullptr, nullptr);
}

// ---------------------------------------------------------------------------
// Attention: 128 threads (4 warps x 32 q-rows), q-tile 128, k-tile 64.
// Each warp spans the FULL 64-key width -> score C-fragments are reused
// in-register as A-fragments for PV (no P smem round trip).
// K/V/mask double-buffered via cp.async; Q staged once.
// Streaming softmax (logits clamped to [-50,50], no max subtraction).
// ---------------------------------------------------------------------------
#define AT_QH    0
#define AT_QL    18432                 // 128*144
#define AT_ST    36864
#define AT_ARR   9216                  // 64*144
#define AT_STAGE (4*AT_ARR)            // Kh,Kl,Vh,Vl
#define AT_MSK   (AT_ST + 2*AT_STAGE)  // 110592
#define ATT_SMEM (AT_MSK + 512)

__global__ __launch_bounds__(128, 2) void attn_ca(const int* __restrict__ mask)
{
    extern __shared__ __align__(16) unsigned char sm[];
    const int t = threadIdx.x, lane = t & 31, w = t >> 5;
    const int gid = lane >> 2, tig = lane & 3;
    const int q0 = blockIdx.x * 128, h = blockIdx.y, b = blockIdx.z;
    const size_t base = ((size_t)(b*NH + h)) * SL * DH;
    const uint32_t smb = smem_u32(sm);
    const uint32_t sQh = smb + AT_QH, sQl = smb + AT_QL;

    // Q prefetch (group 0): 2 arrays x 128 rows x 8 granules
    #pragma unroll
    for (int i = 0; i < 16; i++) {
        const int g = t + i * 128;
        const int arr = g >> 10, rem = g & 1023;
        const int r = rem >> 3, cg = rem & 7;
        const __nv_bfloat16* src = (arr ? g_Ql : g_Qh) + base + (size_t)(q0 + r)*DH + cg*8;
        cp16(smb + arr*18432 + r*144 + cg*16, src);
    }
    CP_COMMIT;

    auto prefetch = [&](int stage, int kt) {
        const int kb = kt * 64;
        const uint32_t stb = smb + AT_ST + stage * AT_STAGE;
        #pragma unroll
        for (int i = 0; i < 16; i++) {
            const int g = t + i * 128;
            const int arr = g >> 9, rem = g & 511;
            const int r = rem >> 3, cg = rem & 7;
            const __nv_bfloat16* src =
                (arr == 0) ? g_Kh + base + (size_t)(kb + r)*DH + cg*8 :
                (arr == 1) ? g_Kl + base + (size_t)(kb + r)*DH + cg*8 :
                (arr == 2) ? g_Vh + base + (size_t)(kb + r)*DH + cg*8 :
                             g_Vl + base + (size_t)(kb + r)*DH + cg*8;
            cp16(stb + arr*AT_ARR + r*144 + cg*16, src);
        }
        if (t < 16) cp16(smb + AT_MSK + stage*256 + t*16, mask + (size_t)b*SL + kb + t*4);
        CP_COMMIT;
    };

    prefetch(0, 0);
    prefetch(1, 1);

    float o[2][8][4];
    #pragma unroll
    for (int mi = 0; mi < 2; mi++)
        #pragma unroll
        for (int nd = 0; nd < 8; nd++)
            #pragma unroll
            for (int r = 0; r < 4; r++) o[mi][nd][r] = 0.0f;
    float den[4] = {0.f, 0.f, 0.f, 0.f};

    for (int kt = 0; kt < 32; kt++) {
        if (kt < 30) { CP_WAIT1; } else { CP_WAIT0; }
        __syncthreads();
        const uint32_t stb = smb + AT_ST + (kt & 1) * AT_STAGE;
        const uint32_t sKh = stb, sKl = stb + AT_ARR;
        const uint32_t sVh = stb + 2*AT_ARR, sVl = stb + 3*AT_ARR;
        const int* mk = (const int*)(sm + AT_MSK + (kt & 1)*256);

        // ---- QK scores: warp tile 32q x 64k ----
        float cS[2][8][4];
        #pragma unroll
        for (int mi = 0; mi < 2; mi++)
            #pragma unroll
            for (int nj = 0; nj < 8; nj++)
                #pragma unroll
                for (int r = 0; r < 4; r++) cS[mi][nj][r] = 0.0f;

        #pragma unroll
        for (int ks = 0; ks < 4; ks++) {
            uint32_t ah[2][4], al_[2][4];
            #pragma unroll
            for (int mi = 0; mi < 2; mi++) {
                const uint32_t off = (uint32_t)((w*32 + mi*16 + (lane & 15))*144
                                     + ks*32 + (lane >> 4)*16);
                ldm4(ah[mi], sQh + off);
                ldm4(al_[mi], sQl + off);
            }
            #pragma unroll
            for (int nj = 0; nj < 8; nj++) {
                uint32_t kh[2], kl[2];
                const uint32_t off = (uint32_t)((nj*8 + (lane & 7))*144
                                     + ks*32 + ((lane >> 3) & 1)*16);
                ldm2(kh, sKh + off);
                ldm2(kl, sKl + off);
                #pragma unroll
                for (int mi = 0; mi < 2; mi++) {
                    mma_bf(cS[mi][nj], ah[mi], kh);
                    mma_bf(cS[mi][nj], ah[mi], kl);
                    mma_bf(cS[mi][nj], al_[mi], kh);
                }
            }
        }

        // ---- softmax numerator; pack P into A-fragments (C->A identity) ----
        uint32_t aPh[2][4][4], aPl[2][4][4];
        float rs[4] = {0.f, 0.f, 0.f, 0.f};
        #pragma unroll
        for (int mi = 0; mi < 2; mi++) {
            #pragma unroll
            for (int nj = 0; nj < 8; nj++) {
                const int mA = mk[nj*8 + 2*tig], mB = mk[nj*8 + 2*tig + 1];
                float p[4];
                #pragma unroll
                for (int r = 0; r < 4; r++) {
                    float s = cS[mi][nj][r] * 0.125f;
                    s = fminf(fmaxf(s, -50.0f), 50.0f);
                    s = ((r & 1) ? mB : mA) ? s : -50.0f;
                    p[r] = __expf(s);
                }
                rs[mi*2+0] += p[0] + p[1];
                rs[mi*2+1] += p[2] + p[3];
                const float h0f = bfhi(p[0]), h1f = bfhi(p[1]);
                const float h2f = bfhi(p[2]), h3f = bfhi(p[3]);
                aPh[mi][nj >> 1][(nj & 1)*2 + 0] = pk(h0f, h1f);
                aPh[mi][nj >> 1][(nj & 1)*2 + 1] = pk(h2f, h3f);
                aPl[mi][nj >> 1][(nj & 1)*2 + 0] = pk(p[0]-h0f, p[1]-h1f);
                aPl[mi][nj >> 1][(nj & 1)*2 + 1] = pk(p[2]-h2f, p[3]-h3f);
            }
        }
        #pragma unroll
        for (int i = 0; i < 4; i++) {
            float r = rs[i];
            r += __shfl_xor_sync(0xffffffffu, r, 1, 4);
            r += __shfl_xor_sync(0xffffffffu, r, 2, 4);
            den[i] += r;
        }

        // ---- PV: O += P V (P from registers) ----
        #pragma unroll
        for (int ks = 0; ks < 4; ks++) {
            #pragma unroll
            for (int nd = 0; nd < 8; nd++) {
                uint32_t vh[2], vl[2];
                const uint32_t off = (uint32_t)((ks*16 + (lane & 7) + ((lane >> 3) & 1)*8)*144
                                     + nd*16);
                ldm2t(vh, sVh + off);
                ldm2t(vl, sVl + off);
                #pragma unroll
                for (int mi = 0; mi < 2; mi++) {
                    mma_bf(o[mi][nd], aPh[mi][ks], vh);
                    mma_bf(o[mi][nd], aPh[mi][ks], vl);
                    mma_bf(o[mi][nd], aPl[mi][ks], vh);
                }
            }
        }

        __syncthreads();
        if (kt + 2 < 32) prefetch(kt & 1, kt + 2);
    }

    // ---- epilogue: normalize, split hi/lo, write [B,S,HID] ----
    #pragma unroll
    for (int mi = 0; mi < 2; mi++) {
        const float inv0 = 1.0f / den[mi*2], inv1 = 1.0f / den[mi*2+1];
        const int r0 = q0 + w*32 + mi*16 + gid, r1 = r0 + 8;
        #pragma unroll
        for (int nd = 0; nd < 8; nd++) {
            const int col = h*DH + nd*8 + 2*tig;
            const float v0 = o[mi][nd][0]*inv0, v1 = o[mi][nd][1]*inv0;
            const float v2 = o[mi][nd][2]*inv1, v3 = o[mi][nd][3]*inv1;
            const float h0f = bfhi(v0), h1f = bfhi(v1);
            const size_t off0 = (size_t)(b*SL + r0)*HID + col;
            *(uint32_t*)&g_Ah[off0] = pk(h0f, h1f);
            *(uint32_t*)&g_Al[off0] = pk(v0 - h0f, v1 - h1f);
            const float h2f = bfhi(v2), h3f = bfhi(v3);
            const size_t off1 = (size_t)(b*SL + r1)*HID + col;
            *(uint32_t*)&g_Ah[off1] = pk(h2f, h3f);
            *(uint32_t*)&g_Al[off1] = pk(v2 - h2f, v3 - h3f);
        }
    }
}

// ---------------------------------------------------------------------------
extern "C" void kernel_launch(void* const* d_in, const int* in_sizes, int n_in,
                              void* d_out, int out_size)
{
    const float* x    = (const float*)d_in[0];
    const int*   mask = (const int*)  d_in[1];
    const float* Wq   = (const float*)d_in[2];
    const float* bq   = (const float*)d_in[3];
    const float* Wk   = (const float*)d_in[4];
    const float* bk   = (const float*)d_in[5];
    const float* Wv   = (const float*)d_in[6];
    const float* bv   = (const float*)d_in[7];
    const float* Wo   = (const float*)d_in[8];
    const float* bo   = (const float*)d_in[9];
    float* out = (float*)d_out;

    cudaFuncSetAttribute(qkv_ca,   cudaFuncAttributeMaxDynamicSharedMemorySize, GEMM_SMEM);
    cudaFuncSetAttribute(oproj_ca, cudaFuncAttributeMaxDynamicSharedMemorySize, GEMM_SMEM);
    cudaFuncSetAttribute(attn_ca,  cudaFuncAttributeMaxDynamicSharedMemorySize, ATT_SMEM);

    split_x_kernel<<<2048, 256>>>(x);
    split_w_kernel<<<dim3(512, 4, 1), 256>>>(Wq, Wk, Wv, Wo);

    qkv_ca<<<dim3(HID/128, MROWS/128, 3), 256, GEMM_SMEM>>>(bq, bk, bv);

    attn_ca<<<dim3(SL/128, NH, NB), 128, ATT_SMEM>>>(mask);

    oproj_ca<<<dim3(HID/128, MROWS/128, 1), 256, GEMM_SMEM>>>(bo, out);
}